// round 11
// baseline (speedup 1.0000x reference)
#include <cuda_runtime.h>
#include <cstdint>

#define S_TOT 32768
#define CH    8
#define NCHUNK (S_TOT / CH)   // 4096

// ---------------- static device scratch (16B aligned) ----------------
__device__ __align__(16) float g_fc1[65536u * 128u];
__device__ __align__(16) float g_xg0[2u * 32768u * 512u];
__device__ __align__(16) float g_xg1[2u * 32768u * 512u];
__device__ __align__(16) float g_h0 [2u * 32768u * 128u];
__device__ __align__(16) float g_y  [2u * 256u * 128u];
__device__ __align__(16) unsigned g_wpk[2u * 512u * 64u];  // Whh packed bf16x2 per layer/row
__device__ int g_prog[8];  // [seq]: L0 chunk flag; [2+seq*2+half]: producer flags

// ---------------- helpers ----------------
__device__ __forceinline__ int ld_acq(const int* p) {
    int v;
    asm volatile("ld.acquire.gpu.b32 %0, [%1];" : "=r"(v) : "l"(p) : "memory");
    return v;
}
__device__ __forceinline__ void st_rel(int* p, int v) {
    asm volatile("st.release.gpu.b32 [%0], %1;" :: "l"(p), "r"(v) : "memory");
}
__device__ __forceinline__ uint32_t s2u(const void* p) {
    return (uint32_t)__cvta_generic_to_shared(p);
}
__device__ __forceinline__ unsigned bf16rn_bits(float f) {
    unsigned u = __float_as_uint(f);
    return ((u + 0x7fffu + ((u >> 16) & 1u)) >> 16) & 0xffffu;
}
// pack (w_even, w_odd): low16 = bf16(w_even) (recover via <<16); whole word as fp32
// best-approximates w_odd (compensated high half) -> zero-instruction odd operand.
__device__ __forceinline__ unsigned pack2(float we, float wo) {
    unsigned lo = bf16rn_bits(we);
    unsigned t  = __float_as_uint(wo) & 0xffff0000u;
    unsigned best = t | lo;
    float bd = fabsf(__uint_as_float(best) - wo);
    unsigned c = (t + 0x10000u) | lo;
    { float d = fabsf(__uint_as_float(c) - wo); if (d < bd) { bd = d; best = c; } }
    c = (t - 0x10000u) | lo;
    { float d = fabsf(__uint_as_float(c) - wo); if (d < bd) { bd = d; best = c; } }
    return best;
}
__device__ __forceinline__ float tanhap(float x) {
    float r;
    asm("tanh.approx.f32 %0, %1;" : "=f"(r) : "f"(x));
    return r;
}
__device__ __forceinline__ float sigap(float x) {
    return fmaf(0.5f, tanhap(0.5f * x), 0.5f);
}
__device__ __forceinline__ void fma2(uint64_t& acc, uint64_t a, uint64_t b) {
    asm("fma.rn.f32x2 %0, %1, %2, %0;" : "+l"(acc) : "l"(a), "l"(b));
}
__device__ __forceinline__ void unpk(uint64_t v, float& lo, float& hi) {
    asm("mov.b64 {%0, %1}, %2;" : "=f"(lo), "=f"(hi) : "l"(v));
}
__device__ __forceinline__ float sum2(uint64_t a) {
    float lo, hi;
    unpk(a, lo, hi);
    return lo + hi;
}
__device__ __forceinline__ void cp16(uint32_t sa, const void* ga) {
    asm volatile("cp.async.ca.shared.global [%0], [%1], 16;" :: "r"(sa), "l"(ga) : "memory");
}
__device__ __forceinline__ void cp_commit() {
    asm volatile("cp.async.commit_group;" ::: "memory");
}
__device__ __forceinline__ void cp_wait1() {
    asm volatile("cp.async.wait_group 1;" ::: "memory");
}
__device__ __forceinline__ void cp_wait0() {
    asm volatile("cp.async.wait_group 0;" ::: "memory");
}

// ---------------- prep: pack Whh rows (both layers), init flags ----------------
__global__ void __launch_bounds__(512) prep_kernel(const float* __restrict__ Whh) {
    int layer = blockIdx.x, j = threadIdx.x;
    const float* row = Whh + ((size_t)layer * 512 + j) * 128;
    unsigned* dst = g_wpk + ((size_t)layer * 512 + j) * 64;
    for (int p = 0; p < 64; p++) dst[p] = pack2(row[2 * p], row[2 * p + 1]);
    if (layer == 0 && j < 8) g_prog[j] = 0;
}

// ---------------- fc1 = relu(x @ Wfc^T + b) ----------------
__global__ void __launch_bounds__(256) fc1_kernel(const float* __restrict__ inp1,
                                                  const float* __restrict__ inp2,
                                                  const float* __restrict__ Wfc,
                                                  const float* __restrict__ bfc) {
    __shared__ __align__(16) float Ws[128][65];
    __shared__ __align__(16) float As[32][64];
    int tid = threadIdx.x;
    for (int i = tid; i < 128 * 64; i += 256) Ws[i >> 6][i & 63] = Wfc[i];
    int r0 = blockIdx.x * 32;
    for (int i = tid; i < 32 * 64; i += 256) {
        int r = r0 + (i >> 6), k = i & 63;
        const float* src = (r < S_TOT) ? (inp1 + (size_t)r * 64)
                                       : (inp2 + (size_t)(r - S_TOT) * 64);
        As[i >> 6][k] = src[k];
    }
    __syncthreads();
    int n = tid & 127, rb = (tid >> 7) * 16;
    float b = bfc[n];
    for (int rr = 0; rr < 16; rr++) {
        float acc = b;
#pragma unroll
        for (int k = 0; k < 64; k++) acc = fmaf(As[rb + rr][k], Ws[n][k], acc);
        g_fc1[(size_t)(r0 + rb + rr) * 128 + n] = fmaxf(acc, 0.f);
    }
}

// ---------------- xg0 = fc1 @ Wih0^T + (bih0+bhh0) ----------------
__global__ void __launch_bounds__(256) xg0_kernel(const float* __restrict__ Wih,
                                                  const float* __restrict__ bih,
                                                  const float* __restrict__ bhh) {
    __shared__ __align__(16) float As[64][68];
    __shared__ __align__(16) float Bs[64][68];
    int m0 = blockIdx.x * 64, n0 = blockIdx.y * 64;
    int tid = threadIdx.x;
    int tx = tid & 15, ty = tid >> 4;
    float acc[4][4] = {};
    for (int kt = 0; kt < 128; kt += 64) {
        for (int i = tid; i < 64 * 16; i += 256) {
            int r = i >> 4, c = (i & 15) * 4;
            float4 v = *(const float4*)(g_fc1 + (size_t)(m0 + r) * 128 + kt + c);
            As[c + 0][r] = v.x; As[c + 1][r] = v.y; As[c + 2][r] = v.z; As[c + 3][r] = v.w;
        }
        for (int i = tid; i < 64 * 16; i += 256) {
            int r = i >> 4, c = (i & 15) * 4;
            float4 v = *(const float4*)(Wih + (size_t)(n0 + r) * 128 + kt + c);
            Bs[c + 0][r] = v.x; Bs[c + 1][r] = v.y; Bs[c + 2][r] = v.z; Bs[c + 3][r] = v.w;
        }
        __syncthreads();
#pragma unroll
        for (int k = 0; k < 64; k++) {
            float4 a4 = *(const float4*)&As[k][ty * 4];
            float4 b4 = *(const float4*)&Bs[k][tx * 4];
            float a[4] = {a4.x, a4.y, a4.z, a4.w};
            float bb[4] = {b4.x, b4.y, b4.z, b4.w};
#pragma unroll
            for (int x = 0; x < 4; x++)
#pragma unroll
                for (int y = 0; y < 4; y++) acc[x][y] = fmaf(a[x], bb[y], acc[x][y]);
        }
        __syncthreads();
    }
#pragma unroll
    for (int x = 0; x < 4; x++) {
        int m = m0 + ty * 4 + x;
#pragma unroll
        for (int y = 0; y < 4; y++) {
            int n = n0 + tx * 4 + y;
            g_xg0[(size_t)m * 512 + n] = acc[x][y] + bih[n] + bhh[n];
        }
    }
}

// ---------------- recurrence: 256 threads, hybrid f32x2+packed, cp.async xg ----------------
// Thread tid: element e = tid>>1, parity p = tid&1.
//   p=0: exact row = gate i (row e),     packed row = gate f (row 128+e)
//   p=1: exact row = gate g (row 256+e), packed row = gate o (row 384+e)
__device__ void rec_h(const float* __restrict__ whh_layer,
                      const unsigned* __restrict__ wpk_layer,
                      const float* __restrict__ xg_src,
                      float* __restrict__ h_stream, float* __restrict__ y_out,
                      const int* wflags, int nwf, int* sflag)
{
    __shared__ __align__(16) float xgs[2][CH][512];
    __shared__ __align__(16) float hsm[2][128];
    int tid = threadIdx.x;
    int e = tid >> 1, p = tid & 1;
    int rowE = p * 256 + e;
    int rowP = rowE + 128;

    uint64_t we[64];
    {
        const uint64_t* wp_ = (const uint64_t*)(whh_layer + (size_t)rowE * 128);
#pragma unroll
        for (int i = 0; i < 64; i++) we[i] = wp_[i];
    }
    unsigned wp[64];
    {
        const unsigned* ws = wpk_layer + (size_t)rowP * 64;
#pragma unroll
        for (int i = 0; i < 64; i++) wp[i] = ws[i];
    }

    uint32_t xg_sm[2];
    xg_sm[0] = s2u(&xgs[0][0][0]);
    xg_sm[1] = s2u(&xgs[1][0][0]);

    if (tid < 128) hsm[0][tid] = 0.f;
    float c = 0.f;

    // prologue: prefetch chunks 0 and 1
    if (nwf) { if (tid < nwf) { while (ld_acq(wflags + tid) < 1) {} } }
    __syncthreads();
    {
        const char* g = (const char*)xg_src;
        uint32_t sb = xg_sm[0] + tid * 16;
#pragma unroll
        for (int r = 0; r < 4; r++) cp16(sb + r * 4096, g + tid * 16 + r * 4096);
        cp_commit();
    }
    if (nwf) { if (tid < nwf) { while (ld_acq(wflags + tid) < 2) {} } __syncthreads(); }
    {
        const char* g = (const char*)(xg_src + (size_t)CH * 512);
        uint32_t sb = xg_sm[1] + tid * 16;
#pragma unroll
        for (int r = 0; r < 4; r++) cp16(sb + r * 4096, g + tid * 16 + r * 4096);
        cp_commit();
    }

    for (int ck = 0; ck < NCHUNK; ck++) {
        if (ck + 1 < NCHUNK) cp_wait1(); else cp_wait0();
        __syncthreads();
        int buf = ck & 1;
#pragma unroll 1
        for (int s = 0; s < CH; s++) {
            int t = ck * CH + s;
            int par = t & 1;
            float xE = xgs[buf][s][rowE];
            float xP = xgs[buf][s][rowP];
            const ulonglong2* h2 = (const ulonglong2*)&hsm[par][0];
            uint64_t a0 = 0ull, a1 = 0ull;
            float b0 = 0.f, b1 = 0.f, b2 = 0.f, b3 = 0.f;
#pragma unroll
            for (int q = 0; q < 32; q++) {
                ulonglong2 hp = h2[q];
                fma2(a0, we[2 * q],     hp.x);
                fma2(a1, we[2 * q + 1], hp.y);
                float h0f, h1f, h2f, h3f;
                unpk(hp.x, h0f, h1f);
                unpk(hp.y, h2f, h3f);
                unsigned w01 = wp[2 * q], w23 = wp[2 * q + 1];
                b0 = fmaf(__uint_as_float(w01 << 16), h0f, b0);
                b1 = fmaf(__uint_as_float(w01),       h1f, b1);
                b2 = fmaf(__uint_as_float(w23 << 16), h2f, b2);
                b3 = fmaf(__uint_as_float(w23),       h3f, b3);
            }
            float vE = (sum2(a0) + sum2(a1)) + xE;
            float vP = ((b0 + b1) + (b2 + b3)) + xP;

            float actE = p ? tanhap(vE) : sigap(vE);   // p0: i   p1: g
            float actP = sigap(vP);                    // p0: f   p1: o
            float sE = __shfl_xor_sync(0xffffffffu, actE, 1);  // p0 receives g
            float sP = __shfl_xor_sync(0xffffffffu, actP, 1);  // p0 receives o
            if (p == 0) {
                c = fmaf(actP, c, actE * sE);          // f*c + i*g
                float h = sP * tanhap(c);              // o * tanh(c)
                hsm[par ^ 1][e] = h;
                if (h_stream) h_stream[(size_t)t * 128 + e] = h;
                if (y_out && t >= S_TOT - 256)
                    y_out[(size_t)(t - (S_TOT - 256)) * 128 + e] = h;
            }
            __syncthreads();
        }
        if (sflag && tid == 0) {
            asm volatile("fence.acq_rel.gpu;" ::: "memory");
            st_rel(sflag, ck + 1);
        }
        if (ck + 2 < NCHUNK) {
            if (nwf) {
                if (tid < nwf) { while (ld_acq(wflags + tid) < ck + 3) {} }
                __syncthreads();
            }
            const char* g = (const char*)(xg_src + (size_t)(ck + 2) * CH * 512);
            uint32_t sb = xg_sm[buf] + tid * 16;
#pragma unroll
            for (int r = 0; r < 4; r++) cp16(sb + r * 4096, g + tid * 16 + r * 4096);
            cp_commit();
        }
    }
}

// ---------------- xg1 producer: 256 threads, 1 row each, full f32x2 ----------------
__device__ void producer(int seq, int half, const float* __restrict__ Wih,
                         const float* __restrict__ bih, const float* __restrict__ bhh) {
    __shared__ __align__(16) float h0s[CH][128];
    int tid = threadIdx.x;
    int row = half * 256 + tid;
    uint64_t w[64];
    {
        const uint64_t* wp_ = (const uint64_t*)(Wih + (size_t)(512 + row) * 128);
#pragma unroll
        for (int i = 0; i < 64; i++) w[i] = wp_[i];
    }
    float b = bih[512 + row] + bhh[512 + row];
    const float* h0 = g_h0 + (size_t)seq * S_TOT * 128;
    float* xg1 = g_xg1 + (size_t)seq * S_TOT * 512;
    const int* wflag = &g_prog[seq];
    int* sflag = &g_prog[2 + seq * 2 + half];

    for (int ck = 0; ck < NCHUNK; ck++) {
        if (tid == 0) { while (ld_acq(wflag) < ck + 1) {} }
        __syncthreads();
        ((float4*)&h0s[0][0])[tid] = ((const float4*)(h0 + (size_t)ck * CH * 128))[tid];
        __syncthreads();
#pragma unroll 1
        for (int ss = 0; ss < CH; ss++) {
            const ulonglong2* h2 = (const ulonglong2*)&h0s[ss][0];
            uint64_t a0 = 0ull, a1 = 0ull;
#pragma unroll
            for (int q = 0; q < 32; q++) {
                ulonglong2 hp = h2[q];
                fma2(a0, w[2 * q],     hp.x);
                fma2(a1, w[2 * q + 1], hp.y);
            }
            xg1[(size_t)(ck * CH + ss) * 512 + row] = (sum2(a0) + sum2(a1)) + b;
        }
        __syncthreads();
        if (tid == 0) {
            asm volatile("fence.acq_rel.gpu;" ::: "memory");
            st_rel(sflag, ck + 1);
        }
    }
}

// ---------------- pipeline: grid padded to 148 (throttle workaround) ----------------
__global__ void __launch_bounds__(256, 1)
pipeline_h(const float* __restrict__ Whh, const float* __restrict__ Wih,
           const float* __restrict__ bih, const float* __restrict__ bhh) {
    int b = blockIdx.x;
    if (b >= 8) return;   // filler CTAs: launch shape only
    int seq = b >> 2, role = b & 3;
    if (role == 0) {
        rec_h(Whh, g_wpk,
              g_xg0 + (size_t)seq * S_TOT * 512,
              g_h0 + (size_t)seq * S_TOT * 128, nullptr,
              nullptr, 0, &g_prog[seq]);
    } else if (role == 3) {
        rec_h(Whh + 512u * 128u, g_wpk + 512u * 64u,
              g_xg1 + (size_t)seq * S_TOT * 512,
              nullptr, g_y + (size_t)seq * 256u * 128u,
              &g_prog[2 + seq * 2], 2, nullptr);
    } else {
        producer(seq, role - 1, Wih, bih, bhh);
    }
}

// ---------------- head ----------------
__global__ void __launch_bounds__(256) head_kernel(const float* __restrict__ Wh,
                                                   const float* __restrict__ bh,
                                                   float* __restrict__ out) {
    int r = threadIdx.x;
    const float* y1 = g_y + (size_t)r * 128;
    const float* y2 = g_y + 256u * 128u + (size_t)r * 128;
    float s1 = 0.f, s2 = 0.f;
#pragma unroll 8
    for (int k = 0; k < 128; k++) {
        float d = y1[k] - y2[k];
        float w = Wh[k];
        s1 = fmaf(w, fmaxf(d, 0.f), s1);
        s2 = fmaf(w, fmaxf(-d, 0.f), s2);
    }
    float b = bh[0];
    float p1 = s1 + b, p2 = s2 + b, pd = (s1 - s2) + b;
    float m = fmaxf(p1, fmaxf(p2, pd));
    float e1 = expf(p1 - m), e2 = expf(p2 - m), e3 = expf(pd - m);
    float inv = 1.f / (e1 + e2 + e3);
    out[r * 3 + 0] = e1 * inv;
    out[r * 3 + 1] = e2 * inv;
    out[r * 3 + 2] = e3 * inv;
}

// ---------------- launch ----------------
extern "C" void kernel_launch(void* const* d_in, const int* in_sizes, int n_in,
                              void* d_out, int out_size) {
    const float* inp1  = (const float*)d_in[0];
    const float* inp2  = (const float*)d_in[1];
    const float* Wfc   = (const float*)d_in[2];
    const float* bfc   = (const float*)d_in[3];
    const float* Wih   = (const float*)d_in[4];
    const float* Whh   = (const float*)d_in[5];
    const float* bih   = (const float*)d_in[6];
    const float* bhh   = (const float*)d_in[7];
    const float* Whead = (const float*)d_in[8];
    const float* bhead = (const float*)d_in[9];
    float* out = (float*)d_out;

    prep_kernel<<<2, 512>>>(Whh);
    fc1_kernel<<<2048, 256>>>(inp1, inp2, Wfc, bfc);
    xg0_kernel<<<dim3(1024, 8), 256>>>(Wih, bih, bhh);
    pipeline_h<<<148, 256>>>(Whh, Wih, bih, bhh);
    head_kernel<<<1, 256>>>(Whead, bhead, out);
}

// round 12
// speedup vs baseline: 1.5217x; 1.5217x over previous
#include <cuda_runtime.h>
#include <cstdint>

#define S_TOT 32768
#define CH    16
#define NCHUNK (S_TOT / CH)

// ---------------- static device scratch (16B aligned) ----------------
__device__ __align__(16) float g_fc1[65536u * 128u];
__device__ __align__(16) float g_xg0[2u * 32768u * 512u];   // PERMUTED: [t][e*4+g]
__device__ __align__(16) float g_xg1[2u * 32768u * 512u];   // PERMUTED
__device__ __align__(16) float g_h0 [2u * 32768u * 128u];
__device__ __align__(16) float g_y  [2u * 256u * 128u];
__device__ __align__(16) unsigned g_wpk[3u * 512u * 64u];   // packed: WhhL0, WhhL1, WihL1
__device__ int g_prog[4];  // [seq]: L0 chunk flag; [2+seq]: producer flag

// ---------------- helpers ----------------
__device__ __forceinline__ int ld_acq(const int* p) {
    int v;
    asm volatile("ld.acquire.gpu.b32 %0, [%1];" : "=r"(v) : "l"(p) : "memory");
    return v;
}
__device__ __forceinline__ void st_rel(int* p, int v) {
    asm volatile("st.release.gpu.b32 [%0], %1;" :: "l"(p), "r"(v) : "memory");
}
__device__ __forceinline__ unsigned bf16rn_bits(float f) {
    unsigned u = __float_as_uint(f);
    return ((u + 0x7fffu + ((u >> 16) & 1u)) >> 16) & 0xffffu;
}
// pack (w_even, w_odd): low16 = bf16(w_even) (recover via <<16); whole word as fp32
// best-approximates w_odd (compensated high half) -> zero-instruction odd operand.
__device__ __forceinline__ unsigned pack2(float we, float wo) {
    unsigned lo = bf16rn_bits(we);
    unsigned t  = __float_as_uint(wo) & 0xffff0000u;
    unsigned best = t | lo;
    float bd = fabsf(__uint_as_float(best) - wo);
    unsigned c = (t + 0x10000u) | lo;
    { float d = fabsf(__uint_as_float(c) - wo); if (d < bd) { bd = d; best = c; } }
    c = (t - 0x10000u) | lo;
    { float d = fabsf(__uint_as_float(c) - wo); if (d < bd) { bd = d; best = c; } }
    return best;
}
__device__ __forceinline__ float tanhap(float x) {
    float r;
    asm("tanh.approx.f32 %0, %1;" : "=f"(r) : "f"(x));
    return r;
}

// 128-MAC packed-bf16 dot: h from smem (broadcast float4), 64 packed regs
__device__ __forceinline__ float dot128p(const float* h, const unsigned* w) {
    const float4* h4 = (const float4*)h;
    float b0 = 0.f, b1 = 0.f, b2 = 0.f, b3 = 0.f;
#pragma unroll
    for (int q = 0; q < 32; q++) {
        float4 hv = h4[q];
        unsigned w01 = w[2 * q], w23 = w[2 * q + 1];
        b0 = fmaf(__uint_as_float(w01 << 16), hv.x, b0);
        b1 = fmaf(__uint_as_float(w01),       hv.y, b1);
        b2 = fmaf(__uint_as_float(w23 << 16), hv.z, b2);
        b3 = fmaf(__uint_as_float(w23),       hv.w, b3);
    }
    return (b0 + b1) + (b2 + b3);
}

// ---------------- prep: pack WhhL0, WhhL1, WihL1; reset flags ----------------
__global__ void __launch_bounds__(512) prep_kernel(const float* __restrict__ Wih,
                                                   const float* __restrict__ Whh) {
    int wsel = blockIdx.x, j = threadIdx.x;
    const float* row;
    if (wsel == 0)      row = Whh + (size_t)j * 128;
    else if (wsel == 1) row = Whh + 512u * 128u + (size_t)j * 128;
    else                row = Wih + 512u * 128u + (size_t)j * 128;
    unsigned* dst = g_wpk + ((size_t)wsel * 512 + j) * 64;
    for (int p = 0; p < 64; p++) dst[p] = pack2(row[2 * p], row[2 * p + 1]);
    if (wsel == 0 && j < 4) g_prog[j] = 0;
}

// ---------------- fc1 = relu(x @ Wfc^T + b) ----------------
__global__ void __launch_bounds__(256) fc1_kernel(const float* __restrict__ inp1,
                                                  const float* __restrict__ inp2,
                                                  const float* __restrict__ Wfc,
                                                  const float* __restrict__ bfc) {
    __shared__ __align__(16) float Ws[128][65];
    __shared__ __align__(16) float As[32][64];
    int tid = threadIdx.x;
    for (int i = tid; i < 128 * 64; i += 256) Ws[i >> 6][i & 63] = Wfc[i];
    int r0 = blockIdx.x * 32;
    for (int i = tid; i < 32 * 64; i += 256) {
        int r = r0 + (i >> 6), k = i & 63;
        const float* src = (r < S_TOT) ? (inp1 + (size_t)r * 64)
                                       : (inp2 + (size_t)(r - S_TOT) * 64);
        As[i >> 6][k] = src[k];
    }
    __syncthreads();
    int n = tid & 127, rb = (tid >> 7) * 16;
    float b = bfc[n];
    for (int rr = 0; rr < 16; rr++) {
        float acc = b;
#pragma unroll
        for (int k = 0; k < 64; k++) acc = fmaf(As[rb + rr][k], Ws[n][k], acc);
        g_fc1[(size_t)(r0 + rb + rr) * 128 + n] = fmaxf(acc, 0.f);
    }
}

// ---------------- xg0 = fc1 @ Wih0^T + (bih0+bhh0), PERMUTED store ----------------
__global__ void __launch_bounds__(256) xg0_kernel(const float* __restrict__ Wih,
                                                  const float* __restrict__ bih,
                                                  const float* __restrict__ bhh) {
    __shared__ __align__(16) float As[64][68];
    __shared__ __align__(16) float Bs[64][68];
    int m0 = blockIdx.x * 64, n0 = blockIdx.y * 64;
    int tid = threadIdx.x;
    int tx = tid & 15, ty = tid >> 4;
    float acc[4][4] = {};
    for (int kt = 0; kt < 128; kt += 64) {
        for (int i = tid; i < 64 * 16; i += 256) {
            int r = i >> 4, c = (i & 15) * 4;
            float4 v = *(const float4*)(g_fc1 + (size_t)(m0 + r) * 128 + kt + c);
            As[c + 0][r] = v.x; As[c + 1][r] = v.y; As[c + 2][r] = v.z; As[c + 3][r] = v.w;
        }
        for (int i = tid; i < 64 * 16; i += 256) {
            int r = i >> 4, c = (i & 15) * 4;
            float4 v = *(const float4*)(Wih + (size_t)(n0 + r) * 128 + kt + c);
            Bs[c + 0][r] = v.x; Bs[c + 1][r] = v.y; Bs[c + 2][r] = v.z; Bs[c + 3][r] = v.w;
        }
        __syncthreads();
#pragma unroll
        for (int k = 0; k < 64; k++) {
            float4 a4 = *(const float4*)&As[k][ty * 4];
            float4 b4 = *(const float4*)&Bs[k][tx * 4];
            float a[4] = {a4.x, a4.y, a4.z, a4.w};
            float bb[4] = {b4.x, b4.y, b4.z, b4.w};
#pragma unroll
            for (int x = 0; x < 4; x++)
#pragma unroll
                for (int y = 0; y < 4; y++) acc[x][y] = fmaf(a[x], bb[y], acc[x][y]);
        }
        __syncthreads();
    }
#pragma unroll
    for (int x = 0; x < 4; x++) {
        int m = m0 + ty * 4 + x;
#pragma unroll
        for (int y = 0; y < 4; y++) {
            int n = n0 + tx * 4 + y;
            int pn = (n & 127) * 4 + (n >> 7);   // permuted position
            g_xg0[(size_t)m * 512 + pn] = acc[x][y] + bih[n] + bhh[n];
        }
    }
}

// ---------------- recurrence: 512 threads, gate-interleaved, 1 barrier/step ----------------
// thread tid: gate g = tid&3, element e = tid>>2, weight row = g*128+e.
// xg is pre-permuted so this thread's xg scalar is xgs[s][tid].
__device__ void rec(const unsigned* __restrict__ wpk_layer,
                    const float* __restrict__ xg_src,
                    float* __restrict__ h_stream, float* __restrict__ y_out,
                    const int* wflag, int* sflag)
{
    __shared__ __align__(16) float xgs[CH][512];
    __shared__ __align__(16) float hsm[2][128];
    int tid = threadIdx.x;
    int g = tid & 3, e = tid >> 2;
    int row = g * 128 + e;

    unsigned w[64];
    {
        const unsigned* ws = wpk_layer + (size_t)row * 64;
#pragma unroll
        for (int i = 0; i < 64; i++) w[i] = ws[i];
    }
    // branchless activation: act = aa*tanh(sel*x)+bb  (g==2 -> tanh, else sigmoid)
    float sel = (g == 2) ? 1.0f : 0.5f;
    float aa  = (g == 2) ? 1.0f : 0.5f;
    float bb  = (g == 2) ? 0.0f : 0.5f;

    if (tid < 256) ((float*)hsm)[tid] = 0.f;
    float c = 0.f;
    __syncthreads();

    for (int t = 0; t < S_TOT; t++) {
        int s = t & (CH - 1);
        if (s == 0) {
            int ck = t >> 4;
            if (wflag) {
                if (tid == 0) { while (ld_acq(wflag) < ck + 1) {} }
                __syncthreads();
            }
            const float4* src = (const float4*)(xg_src + (size_t)ck * CH * 512);
            float4* dst = (float4*)&xgs[0][0];
#pragma unroll
            for (int q = 0; q < 4; q++) dst[tid + 512 * q] = src[tid + 512 * q];
            __syncthreads();
        }
        int par = t & 1;
        float v = dot128p(&hsm[par][0], w) + xgs[s][tid];
        float act = fmaf(aa, tanhap(sel * v), bb);
        float x1 = __shfl_xor_sync(0xffffffffu, act, 1);
        float x2 = __shfl_xor_sync(0xffffffffu, act, 2);
        float x3 = __shfl_xor_sync(0xffffffffu, x1, 2);
        if (g == 0) {
            // act=i, x1=f, x2=g, x3=o
            c = fmaf(x1, c, act * x2);
            float h = x3 * tanhap(c);
            hsm[par ^ 1][e] = h;
            if (h_stream) h_stream[(size_t)t * 128 + e] = h;
            if (y_out && t >= S_TOT - 256)
                y_out[(size_t)(t - (S_TOT - 256)) * 128 + e] = h;
        }
        __syncthreads();
        if (sflag && s == CH - 1 && tid == 0) {
            asm volatile("fence.acq_rel.gpu;" ::: "memory");
            st_rel(sflag, (t >> 4) + 1);
        }
    }
}

// ---------------- xg1 producer: 512 threads, 1 row each, packed, PERMUTED store ----------------
__device__ void producer(int seq, const float* __restrict__ bih, const float* __restrict__ bhh)
{
    __shared__ __align__(16) float h0s[CH][128];
    int tid = threadIdx.x;
    unsigned w[64];
    {
        const unsigned* ws = g_wpk + 2u * 512u * 64u + (size_t)tid * 64;
#pragma unroll
        for (int i = 0; i < 64; i++) w[i] = ws[i];
    }
    float b = bih[512 + tid] + bhh[512 + tid];
    int pn = (tid & 127) * 4 + (tid >> 7);   // permuted output position
    const float* h0 = g_h0 + (size_t)seq * S_TOT * 128;
    float* xg1 = g_xg1 + (size_t)seq * S_TOT * 512;
    const int* wflag = &g_prog[seq];
    int* sflag = &g_prog[2 + seq];

    for (int ck = 0; ck < NCHUNK; ck++) {
        if (tid == 0) { while (ld_acq(wflag) < ck + 1) {} }
        __syncthreads();
        ((float4*)&h0s[0][0])[tid] = ((const float4*)(h0 + (size_t)ck * CH * 128))[tid];
        __syncthreads();
#pragma unroll 1
        for (int ss = 0; ss < CH; ss++) {
            float v = dot128p(&h0s[ss][0], w) + b;
            xg1[(size_t)(ck * CH + ss) * 512 + pn] = v;
        }
        __syncthreads();
        if (tid == 0) {
            asm volatile("fence.acq_rel.gpu;" ::: "memory");
            st_rel(sflag, ck + 1);
        }
    }
}

// ---------------- pipeline: 6 CTAs = 2 seq x {L0rec, producer, L1rec} ----------------
__global__ void __launch_bounds__(512, 1)
pipeline6(const float* __restrict__ bih, const float* __restrict__ bhh) {
    int b = blockIdx.x, seq = b >> 1 >= 1 ? (b / 3) : (b / 3);  // b in [0,6)
    seq = b / 3;
    int role = b % 3;
    if (role == 0) {
        rec(g_wpk, g_xg0 + (size_t)seq * S_TOT * 512,
            g_h0 + (size_t)seq * S_TOT * 128, nullptr,
            nullptr, &g_prog[seq]);
    } else if (role == 1) {
        producer(seq, bih, bhh);
    } else {
        rec(g_wpk + 512u * 64u, g_xg1 + (size_t)seq * S_TOT * 512,
            nullptr, g_y + (size_t)seq * 256u * 128u,
            &g_prog[2 + seq], nullptr);
    }
}

// ---------------- head ----------------
__global__ void __launch_bounds__(256) head_kernel(const float* __restrict__ Wh,
                                                   const float* __restrict__ bh,
                                                   float* __restrict__ out) {
    int r = threadIdx.x;
    const float* y1 = g_y + (size_t)r * 128;
    const float* y2 = g_y + 256u * 128u + (size_t)r * 128;
    float s1 = 0.f, s2 = 0.f;
#pragma unroll 8
    for (int k = 0; k < 128; k++) {
        float d = y1[k] - y2[k];
        float w = Wh[k];
        s1 = fmaf(w, fmaxf(d, 0.f), s1);
        s2 = fmaf(w, fmaxf(-d, 0.f), s2);
    }
    float b = bh[0];
    float p1 = s1 + b, p2 = s2 + b, pd = (s1 - s2) + b;
    float m = fmaxf(p1, fmaxf(p2, pd));
    float e1 = expf(p1 - m), e2 = expf(p2 - m), e3 = expf(pd - m);
    float inv = 1.f / (e1 + e2 + e3);
    out[r * 3 + 0] = e1 * inv;
    out[r * 3 + 1] = e2 * inv;
    out[r * 3 + 2] = e3 * inv;
}

// ---------------- launch ----------------
extern "C" void kernel_launch(void* const* d_in, const int* in_sizes, int n_in,
                              void* d_out, int out_size) {
    const float* inp1  = (const float*)d_in[0];
    const float* inp2  = (const float*)d_in[1];
    const float* Wfc   = (const float*)d_in[2];
    const float* bfc   = (const float*)d_in[3];
    const float* Wih   = (const float*)d_in[4];
    const float* Whh   = (const float*)d_in[5];
    const float* bih   = (const float*)d_in[6];
    const float* bhh   = (const float*)d_in[7];
    const float* Whead = (const float*)d_in[8];
    const float* bhead = (const float*)d_in[9];
    float* out = (float*)d_out;

    prep_kernel<<<3, 512>>>(Wih, Whh);
    fc1_kernel<<<2048, 256>>>(inp1, inp2, Wfc, bfc);
    xg0_kernel<<<dim3(1024, 8), 256>>>(Wih, bih, bhh);
    pipeline6<<<6, 512>>>(bih, bhh);
    head_kernel<<<1, 256>>>(Whead, bhead, out);
}

// round 13
// speedup vs baseline: 2.2306x; 1.4658x over previous
#include <cuda_runtime.h>
#include <cstdint>

#define S_TOT 32768
#define CH    16
#define NCHUNK (S_TOT / CH)

// ---------------- static device scratch (16B aligned) ----------------
__device__ __align__(16) float g_fc1[65536u * 128u];
__device__ __align__(16) float g_xg0[2u * 32768u * 512u];   // PERMUTED: [t][e*4+g]
__device__ __align__(16) float g_xg1[2u * 32768u * 512u];   // PERMUTED
__device__ __align__(16) float g_h0 [2u * 32768u * 128u];
__device__ __align__(16) float g_y  [2u * 256u * 128u];
__device__ __align__(16) unsigned g_wpk[3u * 512u * 64u];   // bf16x2 pairs: WhhL0, WhhL1, WihL1
__device__ int g_prog[4];  // [seq]: L0 chunk flag; [2+seq]: producer flag

// ---------------- helpers ----------------
__device__ __forceinline__ int ld_acq(const int* p) {
    int v;
    asm volatile("ld.acquire.gpu.b32 %0, [%1];" : "=r"(v) : "l"(p) : "memory");
    return v;
}
__device__ __forceinline__ void st_rel(int* p, int v) {
    asm volatile("st.release.gpu.b32 [%0], %1;" :: "l"(p), "r"(v) : "memory");
}
__device__ __forceinline__ unsigned bf16rn_bits(float f) {
    unsigned u = __float_as_uint(f);
    return ((u + 0x7fffu + ((u >> 16) & 1u)) >> 16) & 0xffffu;
}
__device__ __forceinline__ float tanhap(float x) {
    float r;
    asm("tanh.approx.f32 %0, %1;" : "=f"(r) : "f"(x));
    return r;
}
// bf16x2 FMA: acc += a*b (lanewise, bf16 round)
__device__ __forceinline__ void hfma2(unsigned& acc, unsigned a, unsigned b) {
    asm("fma.rn.bf16x2 %0, %1, %2, %0;" : "+r"(acc) : "r"(a), "r"(b));
}
// bf16x2 add via fma with 1.0 multiplier (safe encoding)
__device__ __forceinline__ unsigned hadd2v(unsigned a, unsigned b) {
    unsigned d;
    asm("fma.rn.bf16x2 %0, %1, %2, %3;" : "=r"(d) : "r"(a), "r"(0x3F803F80u), "r"(b));
    return d;
}
__device__ __forceinline__ float bf_lo(unsigned w) { return __uint_as_float(w << 16); }
__device__ __forceinline__ float bf_hi(unsigned w) { return __uint_as_float(w & 0xffff0000u); }
// pack two f32 into bf16x2 (a -> lo, b -> hi)
__device__ __forceinline__ unsigned packbf2(float a, float b) {
    unsigned d;
    asm("cvt.rn.bf16x2.f32 %0, %1, %2;" : "=r"(d) : "f"(b), "f"(a));  // first src -> hi
    return d;
}

// bf16x2 dot over 128 values: h (smem, 64 words), w (64 regs) -> f32
__device__ __forceinline__ float dotbf(const unsigned* hsm_w, const unsigned* w) {
    const uint4* h4 = (const uint4*)hsm_w;   // 16 x 16B
    unsigned acc[8] = {0u, 0u, 0u, 0u, 0u, 0u, 0u, 0u};
#pragma unroll
    for (int q = 0; q < 16; q++) {
        uint4 hp = h4[q];
        int k = q * 4;
        hfma2(acc[k & 7],       w[k],     hp.x);
        hfma2(acc[(k + 1) & 7], w[k + 1], hp.y);
        hfma2(acc[(k + 2) & 7], w[k + 2], hp.z);
        hfma2(acc[(k + 3) & 7], w[k + 3], hp.w);
    }
    unsigned s0 = hadd2v(acc[0], acc[4]);
    unsigned s1 = hadd2v(acc[1], acc[5]);
    unsigned s2 = hadd2v(acc[2], acc[6]);
    unsigned s3 = hadd2v(acc[3], acc[7]);
    return ((bf_lo(s0) + bf_hi(s0)) + (bf_lo(s1) + bf_hi(s1)))
         + ((bf_lo(s2) + bf_hi(s2)) + (bf_lo(s3) + bf_hi(s3)));
}

// ---------------- prep: bf16x2-pack WhhL0, WhhL1, WihL1; reset flags ----------------
__global__ void __launch_bounds__(512) prep_kernel(const float* __restrict__ Wih,
                                                   const float* __restrict__ Whh) {
    int wsel = blockIdx.x, j = threadIdx.x;
    const float* row;
    if (wsel == 0)      row = Whh + (size_t)j * 128;
    else if (wsel == 1) row = Whh + 512u * 128u + (size_t)j * 128;
    else                row = Wih + 512u * 128u + (size_t)j * 128;
    unsigned* dst = g_wpk + ((size_t)wsel * 512 + j) * 64;
    for (int p = 0; p < 64; p++)
        dst[p] = bf16rn_bits(row[2 * p]) | (bf16rn_bits(row[2 * p + 1]) << 16);
    if (wsel == 0 && j < 4) g_prog[j] = 0;
}

// ---------------- fc1 = relu(x @ Wfc^T + b) ----------------
__global__ void __launch_bounds__(256) fc1_kernel(const float* __restrict__ inp1,
                                                  const float* __restrict__ inp2,
                                                  const float* __restrict__ Wfc,
                                                  const float* __restrict__ bfc) {
    __shared__ __align__(16) float Ws[128][65];
    __shared__ __align__(16) float As[32][64];
    int tid = threadIdx.x;
    for (int i = tid; i < 128 * 64; i += 256) Ws[i >> 6][i & 63] = Wfc[i];
    int r0 = blockIdx.x * 32;
    for (int i = tid; i < 32 * 64; i += 256) {
        int r = r0 + (i >> 6), k = i & 63;
        const float* src = (r < S_TOT) ? (inp1 + (size_t)r * 64)
                                       : (inp2 + (size_t)(r - S_TOT) * 64);
        As[i >> 6][k] = src[k];
    }
    __syncthreads();
    int n = tid & 127, rb = (tid >> 7) * 16;
    float b = bfc[n];
    for (int rr = 0; rr < 16; rr++) {
        float acc = b;
#pragma unroll
        for (int k = 0; k < 64; k++) acc = fmaf(As[rb + rr][k], Ws[n][k], acc);
        g_fc1[(size_t)(r0 + rb + rr) * 128 + n] = fmaxf(acc, 0.f);
    }
}

// ---------------- xg0 = fc1 @ Wih0^T + (bih0+bhh0), PERMUTED store ----------------
__global__ void __launch_bounds__(256) xg0_kernel(const float* __restrict__ Wih,
                                                  const float* __restrict__ bih,
                                                  const float* __restrict__ bhh) {
    __shared__ __align__(16) float As[64][68];
    __shared__ __align__(16) float Bs[64][68];
    int m0 = blockIdx.x * 64, n0 = blockIdx.y * 64;
    int tid = threadIdx.x;
    int tx = tid & 15, ty = tid >> 4;
    float acc[4][4] = {};
    for (int kt = 0; kt < 128; kt += 64) {
        for (int i = tid; i < 64 * 16; i += 256) {
            int r = i >> 4, c = (i & 15) * 4;
            float4 v = *(const float4*)(g_fc1 + (size_t)(m0 + r) * 128 + kt + c);
            As[c + 0][r] = v.x; As[c + 1][r] = v.y; As[c + 2][r] = v.z; As[c + 3][r] = v.w;
        }
        for (int i = tid; i < 64 * 16; i += 256) {
            int r = i >> 4, c = (i & 15) * 4;
            float4 v = *(const float4*)(Wih + (size_t)(n0 + r) * 128 + kt + c);
            Bs[c + 0][r] = v.x; Bs[c + 1][r] = v.y; Bs[c + 2][r] = v.z; Bs[c + 3][r] = v.w;
        }
        __syncthreads();
#pragma unroll
        for (int k = 0; k < 64; k++) {
            float4 a4 = *(const float4*)&As[k][ty * 4];
            float4 b4 = *(const float4*)&Bs[k][tx * 4];
            float a[4] = {a4.x, a4.y, a4.z, a4.w};
            float bb[4] = {b4.x, b4.y, b4.z, b4.w};
#pragma unroll
            for (int x = 0; x < 4; x++)
#pragma unroll
                for (int y = 0; y < 4; y++) acc[x][y] = fmaf(a[x], bb[y], acc[x][y]);
        }
        __syncthreads();
    }
#pragma unroll
    for (int x = 0; x < 4; x++) {
        int m = m0 + ty * 4 + x;
#pragma unroll
        for (int y = 0; y < 4; y++) {
            int n = n0 + tx * 4 + y;
            int pn = (n & 127) * 4 + (n >> 7);   // permuted position
            g_xg0[(size_t)m * 512 + pn] = acc[x][y] + bih[n] + bhh[n];
        }
    }
}

// ---------------- recurrence: 512 threads, gate-interleaved, HFMA2 dot ----------------
// thread tid: gate g = tid&3, element e = tid>>2, weight row = g*128+e.
__device__ void rec(const unsigned* __restrict__ wpk_layer,
                    const float* __restrict__ xg_src,
                    float* __restrict__ h_stream, float* __restrict__ y_out,
                    const int* wflag, int* sflag)
{
    __shared__ __align__(16) float xgs[CH][512];
    __shared__ __align__(16) unsigned short hbf[2][128];   // h as bf16
    int tid = threadIdx.x;
    int g = tid & 3, e = tid >> 2;
    int row = g * 128 + e;

    unsigned w[64];
    {
        const unsigned* ws = wpk_layer + (size_t)row * 64;
#pragma unroll
        for (int i = 0; i < 64; i++) w[i] = ws[i];
    }
    // branchless activation: act = aa*tanh(sel*x)+bb  (g==2 -> tanh, else sigmoid)
    float sel = (g == 2) ? 1.0f : 0.5f;
    float aa  = (g == 2) ? 1.0f : 0.5f;
    float bb  = (g == 2) ? 0.0f : 0.5f;

    if (tid < 256) ((unsigned short*)hbf)[tid] = 0;
    float c = 0.f;
    __syncthreads();

    for (int t = 0; t < S_TOT; t++) {
        int s = t & (CH - 1);
        if (s == 0) {
            int ck = t >> 4;
            if (wflag) {
                if (tid == 0) { while (ld_acq(wflag) < ck + 1) {} }
                __syncthreads();
            }
            const float4* src = (const float4*)(xg_src + (size_t)ck * CH * 512);
            float4* dst = (float4*)&xgs[0][0];
#pragma unroll
            for (int q = 0; q < 4; q++) dst[tid + 512 * q] = src[tid + 512 * q];
            __syncthreads();
        }
        int par = t & 1;
        float v = dotbf((const unsigned*)&hbf[par][0], w) + xgs[s][tid];
        float act = fmaf(aa, tanhap(sel * v), bb);
        float x1 = __shfl_xor_sync(0xffffffffu, act, 1);
        float x2 = __shfl_xor_sync(0xffffffffu, act, 2);
        float x3 = __shfl_xor_sync(0xffffffffu, x1, 2);
        if (g == 0) {
            // act=i, x1=f, x2=g, x3=o
            c = fmaf(x1, c, act * x2);
            float h = x3 * tanhap(c);
            unsigned short hb;
            asm("cvt.rn.bf16.f32 %0, %1;" : "=h"(hb) : "f"(h));
            hbf[par ^ 1][e] = hb;
            if (h_stream) h_stream[(size_t)t * 128 + e] = h;
            if (y_out && t >= S_TOT - 256)
                y_out[(size_t)(t - (S_TOT - 256)) * 128 + e] = h;
        }
        __syncthreads();
        if (sflag && s == CH - 1 && tid == 0) {
            asm volatile("fence.acq_rel.gpu;" ::: "memory");
            st_rel(sflag, (t >> 4) + 1);
        }
    }
}

// ---------------- xg1 producer: 512 threads, 1 row each, HFMA2, PERMUTED store ----------------
__device__ void producer(int seq, const float* __restrict__ bih, const float* __restrict__ bhh)
{
    __shared__ __align__(16) unsigned h0bf[CH * 64];   // h0 chunk as bf16x2 words
    int tid = threadIdx.x;
    unsigned w[64];
    {
        const unsigned* ws = g_wpk + 2u * 512u * 64u + (size_t)tid * 64;
#pragma unroll
        for (int i = 0; i < 64; i++) w[i] = ws[i];
    }
    float b = bih[512 + tid] + bhh[512 + tid];
    int pn = (tid & 127) * 4 + (tid >> 7);   // permuted output position
    const float* h0 = g_h0 + (size_t)seq * S_TOT * 128;
    float* xg1 = g_xg1 + (size_t)seq * S_TOT * 512;
    const int* wflag = &g_prog[seq];
    int* sflag = &g_prog[2 + seq];

    for (int ck = 0; ck < NCHUNK; ck++) {
        if (tid == 0) { while (ld_acq(wflag) < ck + 1) {} }
        __syncthreads();
        {
            float4 hv = ((const float4*)(h0 + (size_t)ck * CH * 128))[tid];
            h0bf[tid * 2]     = packbf2(hv.x, hv.y);
            h0bf[tid * 2 + 1] = packbf2(hv.z, hv.w);
        }
        __syncthreads();
#pragma unroll 1
        for (int ss = 0; ss < CH; ss++) {
            float v = dotbf(&h0bf[ss * 64], w) + b;
            xg1[(size_t)(ck * CH + ss) * 512 + pn] = v;
        }
        __syncthreads();
        if (tid == 0) {
            asm volatile("fence.acq_rel.gpu;" ::: "memory");
            st_rel(sflag, ck + 1);
        }
    }
}

// ---------------- pipeline: 6 CTAs = 2 seq x {L0rec, producer, L1rec} ----------------
__global__ void __launch_bounds__(512, 1)
pipeline6(const float* __restrict__ bih, const float* __restrict__ bhh) {
    int b = blockIdx.x;
    int seq = b / 3, role = b % 3;
    if (role == 0) {
        rec(g_wpk, g_xg0 + (size_t)seq * S_TOT * 512,
            g_h0 + (size_t)seq * S_TOT * 128, nullptr,
            nullptr, &g_prog[seq]);
    } else if (role == 1) {
        producer(seq, bih, bhh);
    } else {
        rec(g_wpk + 512u * 64u, g_xg1 + (size_t)seq * S_TOT * 512,
            nullptr, g_y + (size_t)seq * 256u * 128u,
            &g_prog[2 + seq], nullptr);
    }
}

// ---------------- head ----------------
__global__ void __launch_bounds__(256) head_kernel(const float* __restrict__ Wh,
                                                   const float* __restrict__ bh,
                                                   float* __restrict__ out) {
    int r = threadIdx.x;
    const float* y1 = g_y + (size_t)r * 128;
    const float* y2 = g_y + 256u * 128u + (size_t)r * 128;
    float s1 = 0.f, s2 = 0.f;
#pragma unroll 8
    for (int k = 0; k < 128; k++) {
        float d = y1[k] - y2[k];
        float w = Wh[k];
        s1 = fmaf(w, fmaxf(d, 0.f), s1);
        s2 = fmaf(w, fmaxf(-d, 0.f), s2);
    }
    float b = bh[0];
    float p1 = s1 + b, p2 = s2 + b, pd = (s1 - s2) + b;
    float m = fmaxf(p1, fmaxf(p2, pd));
    float e1 = expf(p1 - m), e2 = expf(p2 - m), e3 = expf(pd - m);
    float inv = 1.f / (e1 + e2 + e3);
    out[r * 3 + 0] = e1 * inv;
    out[r * 3 + 1] = e2 * inv;
    out[r * 3 + 2] = e3 * inv;
}

// ---------------- launch ----------------
extern "C" void kernel_launch(void* const* d_in, const int* in_sizes, int n_in,
                              void* d_out, int out_size) {
    const float* inp1  = (const float*)d_in[0];
    const float* inp2  = (const float*)d_in[1];
    const float* Wfc   = (const float*)d_in[2];
    const float* bfc   = (const float*)d_in[3];
    const float* Wih   = (const float*)d_in[4];
    const float* Whh   = (const float*)d_in[5];
    const float* bih   = (const float*)d_in[6];
    const float* bhh   = (const float*)d_in[7];
    const float* Whead = (const float*)d_in[8];
    const float* bhead = (const float*)d_in[9];
    float* out = (float*)d_out;

    prep_kernel<<<3, 512>>>(Wih, Whh);
    fc1_kernel<<<2048, 256>>>(inp1, inp2, Wfc, bfc);
    xg0_kernel<<<dim3(1024, 8), 256>>>(Wih, bih, bhh);
    pipeline6<<<6, 512>>>(bih, bhh);
    head_kernel<<<1, 256>>>(Whead, bhead, out);
}

// round 15
// speedup vs baseline: 2.4660x; 1.1055x over previous
#include <cuda_runtime.h>
#include <cstdint>

#define S_TOT 32768
#define CH    16
#define NCHUNK (S_TOT / CH)

// ---------------- static device scratch (16B aligned) ----------------
__device__ __align__(16) float g_fc1[65536u * 128u];
__device__ __align__(16) float g_xg0[2u * 32768u * 512u];   // PERMUTED: [t][e*4+g]
__device__ __align__(16) float g_xg1[2u * 32768u * 512u];   // PERMUTED
__device__ __align__(16) float g_h0 [2u * 32768u * 128u];
__device__ __align__(16) float g_y  [2u * 256u * 128u];
__device__ __align__(16) unsigned g_wpk[3u * 512u * 64u];   // bf16x2 pairs: WhhL0, WhhL1, WihL1
__device__ int g_prog[4];  // [seq]: L0 chunk flag; [2+seq]: producer flag

// ---------------- helpers ----------------
__device__ __forceinline__ int ld_acq(const int* p) {
    int v;
    asm volatile("ld.acquire.gpu.b32 %0, [%1];" : "=r"(v) : "l"(p) : "memory");
    return v;
}
__device__ __forceinline__ void st_rel(int* p, int v) {
    asm volatile("st.release.gpu.b32 [%0], %1;" :: "l"(p), "r"(v) : "memory");
}
__device__ __forceinline__ unsigned bf16rn_bits(float f) {
    unsigned u = __float_as_uint(f);
    return ((u + 0x7fffu + ((u >> 16) & 1u)) >> 16) & 0xffffu;
}
__device__ __forceinline__ float tanhap(float x) {
    float r;
    asm("tanh.approx.f32 %0, %1;" : "=f"(r) : "f"(x));
    return r;
}
__device__ __forceinline__ float sigap(float x) {
    return fmaf(0.5f, tanhap(0.5f * x), 0.5f);
}
// bf16x2 FMA: acc += a*b (lanewise, bf16 round)
__device__ __forceinline__ void hfma2(unsigned& acc, unsigned a, unsigned b) {
    asm("fma.rn.bf16x2 %0, %1, %2, %0;" : "+r"(acc) : "r"(a), "r"(b));
}
// bf16x2 add via fma with 1.0 multiplier
__device__ __forceinline__ unsigned hadd2v(unsigned a, unsigned b) {
    unsigned d;
    asm("fma.rn.bf16x2 %0, %1, %2, %3;" : "=r"(d) : "r"(a), "r"(0x3F803F80u), "r"(b));
    return d;
}
__device__ __forceinline__ float bf_lo(unsigned w) { return __uint_as_float(w << 16); }
__device__ __forceinline__ float bf_hi(unsigned w) { return __uint_as_float(w & 0xffff0000u); }
__device__ __forceinline__ unsigned packbf2(float a, float b) {
    unsigned d;
    asm("cvt.rn.bf16x2.f32 %0, %1, %2;" : "=r"(d) : "f"(b), "f"(a));  // first src -> hi
    return d;
}

// ---------------- prep: bf16x2-pack WhhL0, WhhL1, WihL1; reset flags ----------------
__global__ void __launch_bounds__(512) prep_kernel(const float* __restrict__ Wih,
                                                   const float* __restrict__ Whh) {
    int wsel = blockIdx.x, j = threadIdx.x;
    const float* row;
    if (wsel == 0)      row = Whh + (size_t)j * 128;
    else if (wsel == 1) row = Whh + 512u * 128u + (size_t)j * 128;
    else                row = Wih + 512u * 128u + (size_t)j * 128;
    unsigned* dst = g_wpk + ((size_t)wsel * 512 + j) * 64;
    for (int p = 0; p < 64; p++)
        dst[p] = bf16rn_bits(row[2 * p]) | (bf16rn_bits(row[2 * p + 1]) << 16);
    if (wsel == 0 && j < 4) g_prog[j] = 0;
}

// ---------------- fc1 = relu(x @ Wfc^T + b) ----------------
__global__ void __launch_bounds__(256) fc1_kernel(const float* __restrict__ inp1,
                                                  const float* __restrict__ inp2,
                                                  const float* __restrict__ Wfc,
                                                  const float* __restrict__ bfc) {
    __shared__ __align__(16) float Ws[128][65];
    __shared__ __align__(16) float As[32][64];
    int tid = threadIdx.x;
    for (int i = tid; i < 128 * 64; i += 256) Ws[i >> 6][i & 63] = Wfc[i];
    int r0 = blockIdx.x * 32;
    for (int i = tid; i < 32 * 64; i += 256) {
        int r = r0 + (i >> 6), k = i & 63;
        const float* src = (r < S_TOT) ? (inp1 + (size_t)r * 64)
                                       : (inp2 + (size_t)(r - S_TOT) * 64);
        As[i >> 6][k] = src[k];
    }
    __syncthreads();
    int n = tid & 127, rb = (tid >> 7) * 16;
    float b = bfc[n];
    for (int rr = 0; rr < 16; rr++) {
        float acc = b;
#pragma unroll
        for (int k = 0; k < 64; k++) acc = fmaf(As[rb + rr][k], Ws[n][k], acc);
        g_fc1[(size_t)(r0 + rb + rr) * 128 + n] = fmaxf(acc, 0.f);
    }
}

// ---------------- xg0 = fc1 @ Wih0^T + (bih0+bhh0), PERMUTED store ----------------
__global__ void __launch_bounds__(256) xg0_kernel(const float* __restrict__ Wih,
                                                  const float* __restrict__ bih,
                                                  const float* __restrict__ bhh) {
    __shared__ __align__(16) float As[64][68];
    __shared__ __align__(16) float Bs[64][68];
    int m0 = blockIdx.x * 64, n0 = blockIdx.y * 64;
    int tid = threadIdx.x;
    int tx = tid & 15, ty = tid >> 4;
    float acc[4][4] = {};
    for (int kt = 0; kt < 128; kt += 64) {
        for (int i = tid; i < 64 * 16; i += 256) {
            int r = i >> 4, c = (i & 15) * 4;
            float4 v = *(const float4*)(g_fc1 + (size_t)(m0 + r) * 128 + kt + c);
            As[c + 0][r] = v.x; As[c + 1][r] = v.y; As[c + 2][r] = v.z; As[c + 3][r] = v.w;
        }
        for (int i = tid; i < 64 * 16; i += 256) {
            int r = i >> 4, c = (i & 15) * 4;
            float4 v = *(const float4*)(Wih + (size_t)(n0 + r) * 128 + kt + c);
            Bs[c + 0][r] = v.x; Bs[c + 1][r] = v.y; Bs[c + 2][r] = v.z; Bs[c + 3][r] = v.w;
        }
        __syncthreads();
#pragma unroll
        for (int k = 0; k < 64; k++) {
            float4 a4 = *(const float4*)&As[k][ty * 4];
            float4 b4 = *(const float4*)&Bs[k][tx * 4];
            float a[4] = {a4.x, a4.y, a4.z, a4.w};
            float bb[4] = {b4.x, b4.y, b4.z, b4.w};
#pragma unroll
            for (int x = 0; x < 4; x++)
#pragma unroll
                for (int y = 0; y < 4; y++) acc[x][y] = fmaf(a[x], bb[y], acc[x][y]);
        }
        __syncthreads();
    }
#pragma unroll
    for (int x = 0; x < 4; x++) {
        int m = m0 + ty * 4 + x;
#pragma unroll
        for (int y = 0; y < 4; y++) {
            int n = n0 + tx * 4 + y;
            int pn = (n & 127) * 4 + (n >> 7);   // permuted position
            g_xg0[(size_t)m * 512 + pn] = acc[x][y] + bih[n] + bhh[n];
        }
    }
}

// ---------------- recurrence: 256 threads, 2 gate rows/thread, HFMA2 ----------------
// thread (e = tid>>1, p = tid&1): p=0 owns rows e (i), 128+e (f);
//                                 p=1 owns rows 256+e (g), 384+e (o).
__device__ void rec(const unsigned* __restrict__ wpk_layer,
                    const float* __restrict__ xg_src,
                    float* __restrict__ h_stream, float* __restrict__ y_out,
                    const int* wflag, int* sflag)
{
    __shared__ __align__(16) float xgs[CH][512];
    __shared__ __align__(16) unsigned short hbf[2][128];   // h as bf16
    int tid = threadIdx.x;                 // 0..255
    int e = tid >> 1, p = tid & 1;
    int row0 = p * 256 + e;                // i (p0) / g (p1)
    int row1 = row0 + 128;                 // f (p0) / o (p1)

    unsigned w0[64], w1[64];
    {
        const unsigned* s0 = wpk_layer + (size_t)row0 * 64;
        const unsigned* s1 = wpk_layer + (size_t)row1 * 64;
#pragma unroll
        for (int i = 0; i < 64; i++) { w0[i] = s0[i]; w1[i] = s1[i]; }
    }
    // row0 activation: p=0 -> sigmoid(i), p=1 -> tanh(g). row1 always sigmoid.
    float sel0 = p ? 1.0f : 0.5f;
    float aa0  = p ? 1.0f : 0.5f;
    float bb0  = p ? 0.0f : 0.5f;

    ((unsigned short*)hbf)[tid] = 0;       // zero both parity buffers (256 shorts)
    float c = 0.f;
    __syncthreads();

    for (int t = 0; t < S_TOT; t++) {
        int s = t & (CH - 1);
        if (s == 0) {
            int ck = t >> 4;
            if (wflag) {
                if (tid == 0) { while (ld_acq(wflag) < ck + 1) {} }
                __syncthreads();
            }
            const float4* src = (const float4*)(xg_src + (size_t)ck * CH * 512);
            float4* dst = (float4*)&xgs[0][0];
#pragma unroll
            for (int q = 0; q < 8; q++) dst[tid + 256 * q] = src[tid + 256 * q];
            __syncthreads();
        }
        int par = t & 1;
        const uint4* h4 = (const uint4*)&hbf[par][0];   // 16 x 16B
        unsigned a0 = 0u, a1 = 0u, a2 = 0u, a3 = 0u;    // row0 accums
        unsigned c0 = 0u, c1 = 0u, c2 = 0u, c3 = 0u;    // row1 accums
#pragma unroll
        for (int q = 0; q < 16; q++) {
            uint4 hp = h4[q];
            hfma2(a0, w0[4 * q],     hp.x);
            hfma2(a1, w0[4 * q + 1], hp.y);
            hfma2(a2, w0[4 * q + 2], hp.z);
            hfma2(a3, w0[4 * q + 3], hp.w);
            hfma2(c0, w1[4 * q],     hp.x);
            hfma2(c1, w1[4 * q + 1], hp.y);
            hfma2(c2, w1[4 * q + 2], hp.z);
            hfma2(c3, w1[4 * q + 3], hp.w);
        }
        unsigned s0w = hadd2v(a0, a2), s1w = hadd2v(a1, a3);
        unsigned t0w = hadd2v(c0, c2), t1w = hadd2v(c1, c3);
        float2 xp = *(const float2*)&xgs[s][e * 4 + 2 * p];
        float v0 = ((bf_lo(s0w) + bf_hi(s0w)) + (bf_lo(s1w) + bf_hi(s1w))) + xp.x;
        float v1 = ((bf_lo(t0w) + bf_hi(t0w)) + (bf_lo(t1w) + bf_hi(t1w))) + xp.y;

        float act0 = fmaf(aa0, tanhap(sel0 * v0), bb0);   // i (p0) / g (p1)
        float act1 = sigap(v1);                           // f (p0) / o (p1)
        float xg_ = __shfl_xor_sync(0xffffffffu, act0, 1);  // p0 receives g
        float xo_ = __shfl_xor_sync(0xffffffffu, act1, 1);  // p0 receives o
        if (p == 0) {
            c = fmaf(act1, c, act0 * xg_);     // f*c + i*g
            float h = xo_ * tanhap(c);         // o * tanh(c)
            unsigned short hb;
            asm("cvt.rn.bf16.f32 %0, %1;" : "=h"(hb) : "f"(h));
            hbf[par ^ 1][e] = hb;
            if (h_stream) h_stream[(size_t)t * 128 + e] = h;
            if (y_out && t >= S_TOT - 256)
                y_out[(size_t)(t - (S_TOT - 256)) * 128 + e] = h;
        }
        __syncthreads();
        if (sflag && s == CH - 1 && tid == 0) {
            asm volatile("fence.acq_rel.gpu;" ::: "memory");
            st_rel(sflag, (t >> 4) + 1);
        }
    }
}

// ---------------- xg1 producer: 256 threads, 2 rows/thread, HFMA2, PERMUTED ----------------
__device__ void producer(int seq, const float* __restrict__ bih, const float* __restrict__ bhh)
{
    __shared__ __align__(16) unsigned h0bf[CH * 64];   // h0 chunk as bf16x2 words
    int tid = threadIdx.x;                 // 0..255, rows tid and tid+256
    unsigned wA[64], wB[64];
    {
        const unsigned* sA = g_wpk + 2u * 512u * 64u + (size_t)tid * 64;
        const unsigned* sB = sA + 256u * 64u;
#pragma unroll
        for (int i = 0; i < 64; i++) { wA[i] = sA[i]; wB[i] = sB[i]; }
    }
    float bA = bih[512 + tid] + bhh[512 + tid];
    float bB = bih[768 + tid] + bhh[768 + tid];
    int pnA = (tid & 127) * 4 + (tid >> 7);
    int pnB = pnA + 2;
    const float* h0 = g_h0 + (size_t)seq * S_TOT * 128;
    float* xg1 = g_xg1 + (size_t)seq * S_TOT * 512;
    const int* wflag = &g_prog[seq];
    int* sflag = &g_prog[2 + seq];

    for (int ck = 0; ck < NCHUNK; ck++) {
        if (tid == 0) { while (ld_acq(wflag) < ck + 1) {} }
        __syncthreads();
        {
            const float4* src = (const float4*)(h0 + (size_t)ck * CH * 128);
#pragma unroll
            for (int q = 0; q < 2; q++) {
                int i = tid + 256 * q;
                float4 hv = src[i];
                h0bf[i * 2]     = packbf2(hv.x, hv.y);
                h0bf[i * 2 + 1] = packbf2(hv.z, hv.w);
            }
        }
        __syncthreads();
#pragma unroll 1
        for (int ss = 0; ss < CH; ss++) {
            const uint4* h4 = (const uint4*)&h0bf[ss * 64];
            unsigned a0 = 0u, a1 = 0u, a2 = 0u, a3 = 0u;
            unsigned c0 = 0u, c1 = 0u, c2 = 0u, c3 = 0u;
#pragma unroll
            for (int q = 0; q < 16; q++) {
                uint4 hp = h4[q];
                hfma2(a0, wA[4 * q],     hp.x);
                hfma2(a1, wA[4 * q + 1], hp.y);
                hfma2(a2, wA[4 * q + 2], hp.z);
                hfma2(a3, wA[4 * q + 3], hp.w);
                hfma2(c0, wB[4 * q],     hp.x);
                hfma2(c1, wB[4 * q + 1], hp.y);
                hfma2(c2, wB[4 * q + 2], hp.z);
                hfma2(c3, wB[4 * q + 3], hp.w);
            }
            unsigned s0w = hadd2v(a0, a2), s1w = hadd2v(a1, a3);
            unsigned t0w = hadd2v(c0, c2), t1w = hadd2v(c1, c3);
            float vA = ((bf_lo(s0w) + bf_hi(s0w)) + (bf_lo(s1w) + bf_hi(s1w))) + bA;
            float vB = ((bf_lo(t0w) + bf_hi(t0w)) + (bf_lo(t1w) + bf_hi(t1w))) + bB;
            float* dst = xg1 + (size_t)(ck * CH + ss) * 512;
            dst[pnA] = vA;
            dst[pnB] = vB;
        }
        __syncthreads();
        if (tid == 0) {
            asm volatile("fence.acq_rel.gpu;" ::: "memory");
            st_rel(sflag, ck + 1);
        }
    }
}

// ---------------- pipeline: 6 CTAs = 2 seq x {L0rec, producer, L1rec} ----------------
__global__ void __launch_bounds__(256, 1)
pipeline6(const float* __restrict__ bih, const float* __restrict__ bhh) {
    int b = blockIdx.x;
    int seq = b / 3, role = b % 3;
    if (role == 0) {
        rec(g_wpk, g_xg0 + (size_t)seq * S_TOT * 512,
            g_h0 + (size_t)seq * S_TOT * 128, nullptr,
            nullptr, &g_prog[seq]);
    } else if (role == 1) {
        producer(seq, bih, bhh);
    } else {
        rec(g_wpk + 512u * 64u, g_xg1 + (size_t)seq * S_TOT * 512,
            nullptr, g_y + (size_t)seq * 256u * 128u,
            &g_prog[2 + seq], nullptr);
    }
}

// ---------------- head ----------------
__global__ void __launch_bounds__(256) head_kernel(const float* __restrict__ Wh,
                                                   const float* __restrict__ bh,
                                                   float* __restrict__ out) {
    int r = threadIdx.x;
    const float* y1 = g_y + (size_t)r * 128;
    const float* y2 = g_y + 256u * 128u + (size_t)r * 128;
    float s1 = 0.f, s2 = 0.f;
#pragma unroll 8
    for (int k = 0; k < 128; k++) {
        float d = y1[k] - y2[k];
        float w = Wh[k];
        s1 = fmaf(w, fmaxf(d, 0.f), s1);
        s2 = fmaf(w, fmaxf(-d, 0.f), s2);
    }
    float b = bh[0];
    float p1 = s1 + b, p2 = s2 + b, pd = (s1 - s2) + b;
    float m = fmaxf(p1, fmaxf(p2, pd));
    float e1 = expf(p1 - m), e2 = expf(p2 - m), e3 = expf(pd - m);
    float inv = 1.f / (e1 + e2 + e3);
    out[r * 3 + 0] = e1 * inv;
    out[r * 3 + 1] = e2 * inv;
    out[r * 3 + 2] = e3 * inv;
}

// ---------------- launch ----------------
extern "C" void kernel_launch(void* const* d_in, const int* in_sizes, int n_in,
                              void* d_out, int out_size) {
    const float* inp1  = (const float*)d_in[0];
    const float* inp2  = (const float*)d_in[1];
    const float* Wfc   = (const float*)d_in[2];
    const float* bfc   = (const float*)d_in[3];
    const float* Wih   = (const float*)d_in[4];
    const float* Whh   = (const float*)d_in[5];
    const float* bih   = (const float*)d_in[6];
    const float* bhh   = (const float*)d_in[7];
    const float* Whead = (const float*)d_in[8];
    const float* bhead = (const float*)d_in[9];
    float* out = (float*)d_out;

    prep_kernel<<<3, 512>>>(Wih, Whh);
    fc1_kernel<<<2048, 256>>>(inp1, inp2, Wfc, bfc);
    xg0_kernel<<<dim3(1024, 8), 256>>>(Wih, bih, bhh);
    pipeline6<<<6, 256>>>(bih, bhh);
    head_kernel<<<1, 256>>>(Whead, bhead, out);
}

// round 16
// speedup vs baseline: 2.6462x; 1.0731x over previous
#include <cuda_runtime.h>
#include <cstdint>

#define S_TOT 32768
#define CH    16
#define NCHUNK (S_TOT / CH)

// ---------------- static device scratch (16B aligned) ----------------
__device__ __align__(16) float g_fc1[65536u * 128u];
__device__ __align__(16) float g_xg0[2u * 32768u * 512u];   // PERMUTED: [t][e*4+g]
__device__ __align__(16) float g_xg1[2u * 32768u * 512u];   // PERMUTED
__device__ __align__(16) unsigned short g_h0bf[2u * 32768u * 128u];  // h0 stream as bf16
__device__ __align__(16) float g_y  [2u * 256u * 128u];
__device__ __align__(16) unsigned g_wpk[3u * 512u * 64u];   // bf16x2 pairs: WhhL0, WhhL1, WihL1
__device__ int g_prog[4];  // [seq]: L0 chunk flag; [2+seq]: producer flag

// ---------------- helpers ----------------
__device__ __forceinline__ int ld_acq(const int* p) {
    int v;
    asm volatile("ld.acquire.gpu.b32 %0, [%1];" : "=r"(v) : "l"(p) : "memory");
    return v;
}
__device__ __forceinline__ void st_rel(int* p, int v) {
    asm volatile("st.release.gpu.b32 [%0], %1;" :: "l"(p), "r"(v) : "memory");
}
__device__ __forceinline__ void barn(int id, int cnt) {
    asm volatile("bar.sync %0, %1;" :: "r"(id), "r"(cnt) : "memory");
}
__device__ __forceinline__ unsigned bf16rn_bits(float f) {
    unsigned u = __float_as_uint(f);
    return ((u + 0x7fffu + ((u >> 16) & 1u)) >> 16) & 0xffffu;
}
__device__ __forceinline__ float tanhap(float x) {
    float r;
    asm("tanh.approx.f32 %0, %1;" : "=f"(r) : "f"(x));
    return r;
}
__device__ __forceinline__ float sigap(float x) {
    return fmaf(0.5f, tanhap(0.5f * x), 0.5f);
}
__device__ __forceinline__ void hfma2(unsigned& acc, unsigned a, unsigned b) {
    asm("fma.rn.bf16x2 %0, %1, %2, %0;" : "+r"(acc) : "r"(a), "r"(b));
}
__device__ __forceinline__ unsigned hadd2v(unsigned a, unsigned b) {
    unsigned d;
    asm("fma.rn.bf16x2 %0, %1, %2, %3;" : "=r"(d) : "r"(a), "r"(0x3F803F80u), "r"(b));
    return d;
}
__device__ __forceinline__ float bf_lo(unsigned w) { return __uint_as_float(w << 16); }
__device__ __forceinline__ float bf_hi(unsigned w) { return __uint_as_float(w & 0xffff0000u); }

// ---------------- prep: bf16x2-pack WhhL0, WhhL1, WihL1; reset flags ----------------
__global__ void __launch_bounds__(512) prep_kernel(const float* __restrict__ Wih,
                                                   const float* __restrict__ Whh) {
    int wsel = blockIdx.x, j = threadIdx.x;
    const float* row;
    if (wsel == 0)      row = Whh + (size_t)j * 128;
    else if (wsel == 1) row = Whh + 512u * 128u + (size_t)j * 128;
    else                row = Wih + 512u * 128u + (size_t)j * 128;
    unsigned* dst = g_wpk + ((size_t)wsel * 512 + j) * 64;
    for (int p = 0; p < 64; p++)
        dst[p] = bf16rn_bits(row[2 * p]) | (bf16rn_bits(row[2 * p + 1]) << 16);
    if (wsel == 0 && j < 4) g_prog[j] = 0;
}

// ---------------- fc1 = relu(x @ Wfc^T + b) ----------------
__global__ void __launch_bounds__(256) fc1_kernel(const float* __restrict__ inp1,
                                                  const float* __restrict__ inp2,
                                                  const float* __restrict__ Wfc,
                                                  const float* __restrict__ bfc) {
    __shared__ __align__(16) float Ws[128][65];
    __shared__ __align__(16) float As[32][64];
    int tid = threadIdx.x;
    for (int i = tid; i < 128 * 64; i += 256) Ws[i >> 6][i & 63] = Wfc[i];
    int r0 = blockIdx.x * 32;
    for (int i = tid; i < 32 * 64; i += 256) {
        int r = r0 + (i >> 6), k = i & 63;
        const float* src = (r < S_TOT) ? (inp1 + (size_t)r * 64)
                                       : (inp2 + (size_t)(r - S_TOT) * 64);
        As[i >> 6][k] = src[k];
    }
    __syncthreads();
    int n = tid & 127, rb = (tid >> 7) * 16;
    float b = bfc[n];
    for (int rr = 0; rr < 16; rr++) {
        float acc = b;
#pragma unroll
        for (int k = 0; k < 64; k++) acc = fmaf(As[rb + rr][k], Ws[n][k], acc);
        g_fc1[(size_t)(r0 + rb + rr) * 128 + n] = fmaxf(acc, 0.f);
    }
}

// ---------------- xg0 = fc1 @ Wih0^T + (bih0+bhh0), PERMUTED store ----------------
__global__ void __launch_bounds__(256) xg0_kernel(const float* __restrict__ Wih,
                                                  const float* __restrict__ bih,
                                                  const float* __restrict__ bhh) {
    __shared__ __align__(16) float As[64][68];
    __shared__ __align__(16) float Bs[64][68];
    int m0 = blockIdx.x * 64, n0 = blockIdx.y * 64;
    int tid = threadIdx.x;
    int tx = tid & 15, ty = tid >> 4;
    float acc[4][4] = {};
    for (int kt = 0; kt < 128; kt += 64) {
        for (int i = tid; i < 64 * 16; i += 256) {
            int r = i >> 4, c = (i & 15) * 4;
            float4 v = *(const float4*)(g_fc1 + (size_t)(m0 + r) * 128 + kt + c);
            As[c + 0][r] = v.x; As[c + 1][r] = v.y; As[c + 2][r] = v.z; As[c + 3][r] = v.w;
        }
        for (int i = tid; i < 64 * 16; i += 256) {
            int r = i >> 4, c = (i & 15) * 4;
            float4 v = *(const float4*)(Wih + (size_t)(n0 + r) * 128 + kt + c);
            Bs[c + 0][r] = v.x; Bs[c + 1][r] = v.y; Bs[c + 2][r] = v.z; Bs[c + 3][r] = v.w;
        }
        __syncthreads();
#pragma unroll
        for (int k = 0; k < 64; k++) {
            float4 a4 = *(const float4*)&As[k][ty * 4];
            float4 b4 = *(const float4*)&Bs[k][tx * 4];
            float a[4] = {a4.x, a4.y, a4.z, a4.w};
            float bb[4] = {b4.x, b4.y, b4.z, b4.w};
#pragma unroll
            for (int x = 0; x < 4; x++)
#pragma unroll
                for (int y = 0; y < 4; y++) acc[x][y] = fmaf(a[x], bb[y], acc[x][y]);
        }
        __syncthreads();
    }
#pragma unroll
    for (int x = 0; x < 4; x++) {
        int m = m0 + ty * 4 + x;
#pragma unroll
        for (int y = 0; y < 4; y++) {
            int n = n0 + tx * 4 + y;
            int pn = (n & 127) * 4 + (n >> 7);   // permuted position
            g_xg0[(size_t)m * 512 + pn] = acc[x][y] + bih[n] + bhh[n];
        }
    }
}

// ---------------- recurrence: 256 compute threads + 1 staging warp ----------------
// compute thread (e = tid>>1, p = tid&1): p=0 owns rows e (i), 128+e (f);
//                                         p=1 owns rows 256+e (g), 384+e (o).
// staging warp (tid 256..287): prefetches xg chunk ck+1, handles flags.
__device__ void rec(char* dsm,
                    const unsigned* __restrict__ wpk_layer,
                    const float* __restrict__ xg_src,
                    unsigned short* __restrict__ h_stream,   // bf16 stream (L0)
                    float* __restrict__ y_out,               // f32 (L1)
                    const int* wflag, int* sflag)
{
    float (*xgs)[CH][512] = (float (*)[CH][512])dsm;                     // 2 x 32KB
    unsigned short (*hbf)[128] = (unsigned short (*)[128])(dsm + 65536); // 2 x 128 bf16
    int tid = threadIdx.x;

    if (tid >= 256) {
        // ---- staging warp ----
        int lt = tid - 256;
        // prologue: load chunk 0
        if (wflag && lt == 0) { while (ld_acq(wflag) < 1) {} }
        __syncwarp();
        {
            const float4* src = (const float4*)xg_src;
            float4* dst = (float4*)&xgs[0][0][0];
            for (int i = lt; i < 2048; i += 32) dst[i] = src[i];
        }
        barn(0, 288);
        for (int ck = 0; ck < NCHUNK; ck++) {
            if (ck + 1 < NCHUNK) {
                if (wflag && lt == 0) { while (ld_acq(wflag) < ck + 2) {} }
                __syncwarp();
                const float4* src = (const float4*)(xg_src + (size_t)(ck + 1) * CH * 512);
                float4* dst = (float4*)&xgs[(ck + 1) & 1][0][0];
                for (int i = lt; i < 2048; i += 32) dst[i] = src[i];
            }
            barn(0, 288);
            if (sflag && lt == 0) {
                asm volatile("fence.acq_rel.gpu;" ::: "memory");
                st_rel(sflag, ck + 1);
            }
        }
        return;
    }

    // ---- compute warps ----
    int e = tid >> 1, p = tid & 1;
    int row0 = p * 256 + e;                // i (p0) / g (p1)
    int row1 = row0 + 128;                 // f (p0) / o (p1)

    unsigned w0[64], w1[64];
    {
        const unsigned* s0 = wpk_layer + (size_t)row0 * 64;
        const unsigned* s1 = wpk_layer + (size_t)row1 * 64;
#pragma unroll
        for (int i = 0; i < 64; i++) { w0[i] = s0[i]; w1[i] = s1[i]; }
    }
    float sel0 = p ? 1.0f : 0.5f;
    float aa0  = p ? 1.0f : 0.5f;
    float bb0  = p ? 0.0f : 0.5f;

    ((unsigned short*)hbf)[tid] = 0;       // zero both parity buffers
    float c = 0.f;
    barn(0, 288);                          // chunk 0 staged

    for (int ck = 0; ck < NCHUNK; ck++) {
        int buf = ck & 1;
#pragma unroll 1
        for (int s = 0; s < CH; s++) {
            int t = ck * CH + s;
            int par = t & 1;
            float2 xp = *(const float2*)&xgs[buf][s][e * 4 + 2 * p];   // hoisted
            const uint4* h4 = (const uint4*)&hbf[par][0];              // 16 x 16B
            unsigned a0 = 0u, a1 = 0u, a2 = 0u, a3 = 0u;               // row0 accums
            unsigned c0 = 0u, c1 = 0u, c2 = 0u, c3 = 0u;               // row1 accums
#pragma unroll
            for (int q = 0; q < 16; q++) {
                uint4 hp = h4[q];
                hfma2(a0, w0[4 * q],     hp.x);
                hfma2(a1, w0[4 * q + 1], hp.y);
                hfma2(a2, w0[4 * q + 2], hp.z);
                hfma2(a3, w0[4 * q + 3], hp.w);
                hfma2(c0, w1[4 * q],     hp.x);
                hfma2(c1, w1[4 * q + 1], hp.y);
                hfma2(c2, w1[4 * q + 2], hp.z);
                hfma2(c3, w1[4 * q + 3], hp.w);
            }
            unsigned s0w = hadd2v(a0, a2), s1w = hadd2v(a1, a3);
            unsigned t0w = hadd2v(c0, c2), t1w = hadd2v(c1, c3);
            float v0 = ((bf_lo(s0w) + bf_hi(s0w)) + (bf_lo(s1w) + bf_hi(s1w))) + xp.x;
            float v1 = ((bf_lo(t0w) + bf_hi(t0w)) + (bf_lo(t1w) + bf_hi(t1w))) + xp.y;

            float act0 = fmaf(aa0, tanhap(sel0 * v0), bb0);   // i (p0) / g (p1)
            float act1 = sigap(v1);                           // f (p0) / o (p1)
            float xg_ = __shfl_xor_sync(0xffffffffu, act0, 1);  // p0 receives g
            float xo_ = __shfl_xor_sync(0xffffffffu, act1, 1);  // p0 receives o
            if (p == 0) {
                c = fmaf(act1, c, act0 * xg_);     // f*c + i*g
                float h = xo_ * tanhap(c);         // o * tanh(c)
                unsigned short hb;
                asm("cvt.rn.bf16.f32 %0, %1;" : "=h"(hb) : "f"(h));
                hbf[par ^ 1][e] = hb;
                if (h_stream) h_stream[(size_t)t * 128 + e] = hb;
                if (y_out && t >= S_TOT - 256)
                    y_out[(size_t)(t - (S_TOT - 256)) * 128 + e] = h;
            }
            if (s != CH - 1) barn(1, 256);   // last step synced by chunk bar
        }
        barn(0, 288);
    }
}

// ---------------- xg1 producer: 256 threads, 2 rows/thread, bf16 input ----------------
__device__ void producer(char* dsm, int seq,
                         const float* __restrict__ bih, const float* __restrict__ bhh)
{
    unsigned* h0bf = (unsigned*)dsm;       // CH*64 bf16x2 words (4KB)
    int tid = threadIdx.x;                 // 0..255, rows tid and tid+256
    unsigned wA[64], wB[64];
    {
        const unsigned* sA = g_wpk + 2u * 512u * 64u + (size_t)tid * 64;
        const unsigned* sB = sA + 256u * 64u;
#pragma unroll
        for (int i = 0; i < 64; i++) { wA[i] = sA[i]; wB[i] = sB[i]; }
    }
    float bA = bih[512 + tid] + bhh[512 + tid];
    float bB = bih[768 + tid] + bhh[768 + tid];
    int pnA = (tid & 127) * 4 + (tid >> 7);
    int pnB = pnA + 2;
    const unsigned* h0w = (const unsigned*)(g_h0bf + (size_t)seq * S_TOT * 128);
    float* xg1 = g_xg1 + (size_t)seq * S_TOT * 512;
    const int* wflag = &g_prog[seq];
    int* sflag = &g_prog[2 + seq];

    for (int ck = 0; ck < NCHUNK; ck++) {
        if (tid == 0) { while (ld_acq(wflag) < ck + 1) {} }
        __syncthreads();
        ((uint4*)h0bf)[tid] = ((const uint4*)(h0w + (size_t)ck * CH * 64))[tid];
        __syncthreads();
#pragma unroll 1
        for (int ss = 0; ss < CH; ss++) {
            const uint4* h4 = (const uint4*)&h0bf[ss * 64];
            unsigned a0 = 0u, a1 = 0u, a2 = 0u, a3 = 0u;
            unsigned c0 = 0u, c1 = 0u, c2 = 0u, c3 = 0u;
#pragma unroll
            for (int q = 0; q < 16; q++) {
                uint4 hp = h4[q];
                hfma2(a0, wA[4 * q],     hp.x);
                hfma2(a1, wA[4 * q + 1], hp.y);
                hfma2(a2, wA[4 * q + 2], hp.z);
                hfma2(a3, wA[4 * q + 3], hp.w);
                hfma2(c0, wB[4 * q],     hp.x);
                hfma2(c1, wB[4 * q + 1], hp.y);
                hfma2(c2, wB[4 * q + 2], hp.z);
                hfma2(c3, wB[4 * q + 3], hp.w);
            }
            unsigned s0w = hadd2v(a0, a2), s1w = hadd2v(a1, a3);
            unsigned t0w = hadd2v(c0, c2), t1w = hadd2v(c1, c3);
            float vA = ((bf_lo(s0w) + bf_hi(s0w)) + (bf_lo(s1w) + bf_hi(s1w))) + bA;
            float vB = ((bf_lo(t0w) + bf_hi(t0w)) + (bf_lo(t1w) + bf_hi(t1w))) + bB;
            float* dst = xg1 + (size_t)(ck * CH + ss) * 512;
            dst[pnA] = vA;
            dst[pnB] = vB;
        }
        __syncthreads();
        if (tid == 0) {
            asm volatile("fence.acq_rel.gpu;" ::: "memory");
            st_rel(sflag, ck + 1);
        }
    }
}

// ---------------- pipeline: 6 CTAs = 2 seq x {L0rec, producer, L1rec} ----------------
__global__ void __launch_bounds__(288, 1)
pipeline6(const float* __restrict__ bih, const float* __restrict__ bhh) {
    extern __shared__ char dsm[];
    int b = blockIdx.x;
    int seq = b / 3, role = b % 3;
    if (role == 0) {
        rec(dsm, g_wpk, g_xg0 + (size_t)seq * S_TOT * 512,
            g_h0bf + (size_t)seq * S_TOT * 128, nullptr,
            nullptr, &g_prog[seq]);
    } else if (role == 1) {
        if (threadIdx.x >= 256) return;   // producer uses 256 threads
        producer(dsm, seq, bih, bhh);
    } else {
        rec(dsm, g_wpk + 512u * 64u, g_xg1 + (size_t)seq * S_TOT * 512,
            nullptr, g_y + (size_t)seq * 256u * 128u,
            &g_prog[2 + seq], nullptr);
    }
}

// ---------------- head ----------------
__global__ void __launch_bounds__(256) head_kernel(const float* __restrict__ Wh,
                                                   const float* __restrict__ bh,
                                                   float* __restrict__ out) {
    int r = threadIdx.x;
    const float* y1 = g_y + (size_t)r * 128;
    const float* y2 = g_y + 256u * 128u + (size_t)r * 128;
    float s1 = 0.f, s2 = 0.f;
#pragma unroll 8
    for (int k = 0; k < 128; k++) {
        float d = y1[k] - y2[k];
        float w = Wh[k];
        s1 = fmaf(w, fmaxf(d, 0.f), s1);
        s2 = fmaf(w, fmaxf(-d, 0.f), s2);
    }
    float b = bh[0];
    float p1 = s1 + b, p2 = s2 + b, pd = (s1 - s2) + b;
    float m = fmaxf(p1, fmaxf(p2, pd));
    float e1 = expf(p1 - m), e2 = expf(p2 - m), e3 = expf(pd - m);
    float inv = 1.f / (e1 + e2 + e3);
    out[r * 3 + 0] = e1 * inv;
    out[r * 3 + 1] = e2 * inv;
    out[r * 3 + 2] = e3 * inv;
}

// ---------------- launch ----------------
extern "C" void kernel_launch(void* const* d_in, const int* in_sizes, int n_in,
                              void* d_out, int out_size) {
    const float* inp1  = (const float*)d_in[0];
    const float* inp2  = (const float*)d_in[1];
    const float* Wfc   = (const float*)d_in[2];
    const float* bfc   = (const float*)d_in[3];
    const float* Wih   = (const float*)d_in[4];
    const float* Whh   = (const float*)d_in[5];
    const float* bih   = (const float*)d_in[6];
    const float* bhh   = (const float*)d_in[7];
    const float* Whead = (const float*)d_in[8];
    const float* bhead = (const float*)d_in[9];
    float* out = (float*)d_out;

    const int DSM = 2 * CH * 512 * 4 + 2 * 128 * 2;   // 66048
    cudaFuncSetAttribute(pipeline6, cudaFuncAttributeMaxDynamicSharedMemorySize, DSM);

    prep_kernel<<<3, 512>>>(Wih, Whh);
    fc1_kernel<<<2048, 256>>>(inp1, inp2, Wfc, bfc);
    xg0_kernel<<<dim3(1024, 8), 256>>>(Wih, bih, bhh);
    pipeline6<<<6, 288, DSM>>>(bih, bhh);
    head_kernel<<<1, 256>>>(Whead, bhead, out);
}